// round 14
// baseline (speedup 1.0000x reference)
#include <cuda_runtime.h>
#include <cuda_fp16.h>
#include <math.h>

#define NP   31752
#define D_   192
#define NA   256
#define LMB  0.1f
#define NSQ  9
#define T_   72
#define NCTA 441
#define NB   64
#define CSTR 264                 // cs row stride in halfs

typedef unsigned long long ull;
typedef unsigned int u32;

// ---------------- static device scratch ----------------
__device__ float  g_A[NA * D_];
__device__ float  g_At[D_ * NA];
__device__ float  g_X[NA * NA];
__device__ float  g_Ma[NA * NA];
__device__ float  g_Mb[NA * NA];
__device__ __half g_XfH[16 * 16 * 32 * 8];    // X frags [s16][t16][lane][8]
__device__ __half g_XfL[16 * 16 * 32 * 8];
__device__ __half g_AfH[12 * 16 * 32 * 8];    // dict frags (q-phase) [s12][t16]
__device__ __half g_AfL[12 * 16 * 32 * 8];
__device__ __half g_AtfH[16 * 12 * 32 * 8];   // dict-T frags (rec) [s16][t12]
__device__ __half g_AtfL[16 * 12 * 32 * 8];
__device__ float  g_fs[16];
__device__ float  g_params[4];
__device__ float  g_rec[(size_t)NP * D_];
__device__ unsigned g_arrive = 0;

// ---------------- helpers ----------------
__device__ __forceinline__ float softthr(float v, float thr) {
    float a = fabsf(v) - thr;
    return a > 0.f ? copysignf(a, v) : 0.f;
}
__device__ __forceinline__ void mma16816(float* d, const u32* a, u32 b0, u32 b1) {
    asm volatile(
        "mma.sync.aligned.m16n8k16.row.col.f32.f16.f16.f32 "
        "{%0,%1,%2,%3}, {%4,%5,%6,%7}, {%8,%9}, {%0,%1,%2,%3};"
        : "+f"(d[0]), "+f"(d[1]), "+f"(d[2]), "+f"(d[3])
        : "r"(a[0]), "r"(a[1]), "r"(a[2]), "r"(a[3]), "r"(b0), "r"(b1));
}

// ---------------- k_reset + grid barrier ----------------
__global__ void k_reset() { if (threadIdx.x == 0) g_arrive = 0; }

__device__ __forceinline__ void gsync(unsigned target) {
    __threadfence();
    __syncthreads();
    if (threadIdx.x == 0) {
        atomicAdd(&g_arrive, 1u);
        while (*((volatile unsigned*)&g_arrive) < target) { }
        __threadfence();
    }
    __syncthreads();
}

// ---------------- k_chain (proven): normalize + Gram + spectral norm ----------------
__global__ void __launch_bounds__(256, 1) k_chain(const float* __restrict__ atoms) {
    __shared__ float AshT[NA * 4];
    __shared__ float red[256];
    const int tid = threadIdx.x;
    const int cta = blockIdx.x;
    const int r0 = cta * 4;
    unsigned bar = 0;

    if (cta == 0 && tid < 16) g_fs[tid] = 0.f;
    {
        int r = tid >> 6, l = tid & 63;
        int row = r0 + r;
        float v0 = atoms[row * D_ + l];
        float v1 = atoms[row * D_ + l + 64];
        float v2 = atoms[row * D_ + l + 128];
        red[tid] = v0 * v0 + v1 * v1 + v2 * v2;
        __syncthreads();
        for (int o = 32; o > 0; o >>= 1) {
            if (l < o) red[tid] += red[tid + o];
            __syncthreads();
        }
        float inv = 1.0f / sqrtf(red[r * 64]);
        float a0 = v0 * inv, a1 = v1 * inv, a2 = v2 * inv;
        g_A[row * D_ + l]       = a0;  g_At[l * NA + row]         = a0;
        g_A[row * D_ + l + 64]  = a1;  g_At[(l + 64) * NA + row]  = a1;
        g_A[row * D_ + l + 128] = a2;  g_At[(l + 128) * NA + row] = a2;
    }
    gsync(++bar * NB);

    {
        for (int i = tid; i < 4 * D_; i += 256) {
            int r = i / D_, k = i % D_;
            AshT[k * 4 + r] = g_A[(r0 + r) * D_ + k];
        }
        __syncthreads();
        int c = tid;
        float acc0 = 0.f, acc1 = 0.f, acc2 = 0.f, acc3 = 0.f;
        for (int k = 0; k < D_; k++) {
            float b = __ldcg(&g_At[k * NA + c]);
            float4 a4 = *(const float4*)&AshT[k * 4];
            acc0 += a4.x * b; acc1 += a4.y * b; acc2 += a4.z * b; acc3 += a4.w * b;
        }
        g_X[(r0 + 0) * NA + c] = acc0;
        g_X[(r0 + 1) * NA + c] = acc1;
        g_X[(r0 + 2) * NA + c] = acc2;
        g_X[(r0 + 3) * NA + c] = acc3;
        float fsum = acc0 * acc0 + acc1 * acc1 + acc2 * acc2 + acc3 * acc3;
#pragma unroll
        for (int o = 16; o > 0; o >>= 1) fsum += __shfl_xor_sync(0xffffffffu, fsum, o);
        if ((tid & 31) == 0) atomicAdd(&g_fs[1], fsum);
        __syncthreads();
    }
    gsync(++bar * NB);

    const float* In = g_X;
    float* Out = g_Ma;
    for (int j = 1; j <= NSQ; j++) {
        float scale = 1.0f / __ldcg(&g_fs[j]);
        for (int i = tid; i < 1024; i += 256) {
            int r = i >> 8, k = i & 255;
            AshT[k * 4 + r] = __ldcg(&In[(r0 + r) * NA + k]);
        }
        __syncthreads();
        int c = tid;
        float acc0 = 0.f, acc1 = 0.f, acc2 = 0.f, acc3 = 0.f;
        for (int k = 0; k < NA; k++) {
            float b = __ldcg(&In[k * NA + c]);
            float4 a4 = *(const float4*)&AshT[k * 4];
            acc0 += a4.x * b; acc1 += a4.y * b; acc2 += a4.z * b; acc3 += a4.w * b;
        }
        acc0 *= scale; acc1 *= scale; acc2 *= scale; acc3 *= scale;
        Out[(r0 + 0) * NA + c] = acc0;
        Out[(r0 + 1) * NA + c] = acc1;
        Out[(r0 + 2) * NA + c] = acc2;
        Out[(r0 + 3) * NA + c] = acc3;
        float fsum = acc0 * acc0 + acc1 * acc1 + acc2 * acc2 + acc3 * acc3;
#pragma unroll
        for (int o = 16; o > 0; o >>= 1) fsum += __shfl_xor_sync(0xffffffffu, fsum, o);
        if ((tid & 31) == 0) atomicAdd(&g_fs[j + 1], fsum);
        const float* nIn = Out;
        Out = (Out == g_Ma) ? g_Mb : g_Ma;
        In = nIn;
        gsync(++bar * NB);
    }

    if (cta == 0) {
        red[tid] = __ldcg(&In[tid * NA + tid]);
        __syncthreads();
        for (int o = 128; o > 0; o >>= 1) {
            if (tid < o) red[tid] += red[tid + o];
            __syncthreads();
        }
        if (tid == 0) {
            double lg = log((double)red[0]);
            for (int j = 1; j <= NSQ; j++)
                lg += (double)(1 << (NSQ - j)) * log((double)__ldcg(&g_fs[j]));
            double L = exp(lg / (double)(1 << NSQ));
            g_params[0] = (float)L;
            g_params[1] = (float)(1.0 / L);
            g_params[2] = (float)((double)LMB / L);
        }
    }
}

// ---------------- merged fragment pre-swizzle (one launch) ----------------
__device__ __forceinline__ void frag_core(__half* dH, __half* dL,
                                          const float* __restrict__ src, int stride,
                                          int s, int t, int lane, size_t sidx) {
    int g = lane >> 2, tg = lane & 3;
    int r = t * 16 + g, k = s * 16 + 2 * tg;
    float v[8];
    v[0] = src[r * stride + k];           v[1] = src[r * stride + k + 1];
    v[2] = src[(r + 8) * stride + k];     v[3] = src[(r + 8) * stride + k + 1];
    v[4] = src[r * stride + k + 8];       v[5] = src[r * stride + k + 9];
    v[6] = src[(r + 8) * stride + k + 8]; v[7] = src[(r + 8) * stride + k + 9];
    u32 ph[4], pl[4];
#pragma unroll
    for (int i = 0; i < 4; i++) {
        __half h0 = __float2half(v[2 * i]);
        __half h1 = __float2half(v[2 * i + 1]);
        __half l0 = __float2half(v[2 * i] - __half2float(h0));
        __half l1 = __float2half(v[2 * i + 1] - __half2float(h1));
        __half2 hh = __halves2half2(h0, h1);
        __half2 ll = __halves2half2(l0, l1);
        ph[i] = *(u32*)&hh; pl[i] = *(u32*)&ll;
    }
    *(uint4*)&dH[sidx * 8] = make_uint4(ph[0], ph[1], ph[2], ph[3]);
    *(uint4*)&dL[sidx * 8] = make_uint4(pl[0], pl[1], pl[2], pl[3]);
}

// blocks 0..31: X (8192 items); 32..55: A (6144); 56..79: At (6144)
__global__ void k_frag() {
    int blk = blockIdx.x;
    if (blk < 32) {
        int id = blk * 256 + threadIdx.x;
        if (id >= 16 * 16 * 32) return;
        int lane = id & 31, t = (id >> 5) & 15, s = id >> 9;
        frag_core(g_XfH, g_XfL, g_X, NA, s, t, lane, (size_t)(s * 16 + t) * 32 + lane);
    } else if (blk < 56) {
        int id = (blk - 32) * 256 + threadIdx.x;
        if (id >= 12 * 16 * 32) return;
        int lane = id & 31, t = (id >> 5) & 15, s = id >> 9;
        frag_core(g_AfH, g_AfL, g_A, D_, s, t, lane, (size_t)(s * 16 + t) * 32 + lane);
    } else {
        int id = (blk - 56) * 256 + threadIdx.x;
        if (id >= 16 * 12 * 32) return;
        int lane = id & 31, rest = id >> 5;
        int t = rest % 12, s = rest / 12;
        frag_core(g_AtfH, g_AtfL, g_At, NA, s, t, lane, (size_t)(s * 12 + t) * 32 + lane);
    }
}

// ---------------- k_ista: HMMA split ISTA (R11-proven direct-LDG mainloop) ----------------
// SMEM: csH 38016 | csL 38016 | qf 73728 | msh 288  -> 150048 bytes
#define CSH_OFF 0
#define CSL_OFF 38016
#define QF_OFF  76032
#define MSH_OFF 149760
#define SM_ISTA 150048

__device__ __forceinline__ void frag_gemm(float (&acc)[2][9][4],
                                          const __half* __restrict__ fH,
                                          const __half* __restrict__ fL,
                                          int nks, const __half* csH, const __half* csL,
                                          int t0, int lane, int g, int tg) {
    const uint4* FH = (const uint4*)fH;
    const uint4* FL = (const uint4*)fL;
    uint4 ah[2], al[2];
    ah[0] = FH[(0 * 16 + t0) * 32 + lane];
    ah[1] = FH[(0 * 16 + t0 + 1) * 32 + lane];
    al[0] = FL[(0 * 16 + t0) * 32 + lane];
    al[1] = FL[(0 * 16 + t0 + 1) * 32 + lane];
    for (int s = 0; s < nks; s++) {
        uint4 nh[2], nl[2];
        if (s + 1 < nks) {
            nh[0] = FH[((s + 1) * 16 + t0) * 32 + lane];
            nh[1] = FH[((s + 1) * 16 + t0 + 1) * 32 + lane];
            nl[0] = FL[((s + 1) * 16 + t0) * 32 + lane];
            nl[1] = FL[((s + 1) * 16 + t0 + 1) * 32 + lane];
        }
        const __half* bh = csH + g * CSTR + s * 16 + 2 * tg;
        const __half* bl = csL + g * CSTR + s * 16 + 2 * tg;
#pragma unroll
        for (int nt = 0; nt < 9; nt++) {
            u32 b0h = *(const u32*)(bh + nt * 8 * CSTR);
            u32 b1h = *(const u32*)(bh + nt * 8 * CSTR + 8);
            u32 b0l = *(const u32*)(bl + nt * 8 * CSTR);
            u32 b1l = *(const u32*)(bl + nt * 8 * CSTR + 8);
            mma16816(acc[0][nt], (const u32*)&ah[0], b0h, b1h);
            mma16816(acc[1][nt], (const u32*)&ah[1], b0h, b1h);
            mma16816(acc[0][nt], (const u32*)&al[0], b0h, b1h);
            mma16816(acc[1][nt], (const u32*)&al[1], b0h, b1h);
            mma16816(acc[0][nt], (const u32*)&ah[0], b0l, b1l);
            mma16816(acc[1][nt], (const u32*)&ah[1], b0l, b1l);
        }
        ah[0] = nh[0]; ah[1] = nh[1]; al[0] = nl[0]; al[1] = nl[1];
    }
}

__global__ void __launch_bounds__(256, 1) k_ista(const float* __restrict__ y) {
    extern __shared__ char smb[];
    __half* csH = (__half*)(smb + CSH_OFF);
    __half* csL = (__half*)(smb + CSL_OFF);
    float* qf = (float*)(smb + QF_OFF);
    float* msh = (float*)(smb + MSH_OFF);
    const int tid = threadIdx.x;
    const int w = tid >> 5, lane = tid & 31, g = lane >> 2, tg = lane & 3;
    const int t0 = 2 * w;
    const int n0 = blockIdx.x * T_;
    const float invL = g_params[1], thr = g_params[2];

    // ---- fused per-patch mean ----
    for (int i = 0; i < 9; i++) {
        int j = w * 9 + i;
        int n = n0 + j;
        int b = n / 3969, r = n % 3969, pi = r / 63, pj = r % 63;
        float s = 0.f;
#pragma unroll
        for (int dd = 0; dd < 6; dd++) {
            int d = lane * 6 + dd;
            int ch = d >> 6, u = (d >> 3) & 7, v = d & 7;
            s += y[((b * 3 + ch) * 256 + pi * 4 + u) * 256 + pj * 4 + v];
        }
#pragma unroll
        for (int o = 16; o > 0; o >>= 1) s += __shfl_xor_sync(0xffffffffu, s, o);
        if (lane == 0) msh[j] = s * (1.f / 192.f);
    }
    __syncthreads();

    // ---- gather centered patches ----
    for (int e = tid; e < 72 * 192; e += 256) {
        int j = e / 192, d = e % 192;
        int n = n0 + j;
        int b = n / 3969, r = n % 3969, pi = r / 63, pj = r % 63;
        int ch = d >> 6, u = (d >> 3) & 7, v = d & 7;
        float pv = y[((b * 3 + ch) * 256 + pi * 4 + u) * 256 + pj * 4 + v] - msh[j];
        __half h = __float2half(pv);
        csH[j * CSTR + d] = h;
        csL[j * CSTR + d] = __float2half(pv - __half2float(h));
    }
    __syncthreads();

    float acc[2][9][4];
    float c_reg[2][9][4];
#pragma unroll
    for (int a = 0; a < 2; a++)
#pragma unroll
        for (int b = 0; b < 9; b++)
#pragma unroll
            for (int e = 0; e < 4; e++) acc[a][b][e] = 0.f;

    // ---- q = A @ p^T : 12 k-chunks ----
    frag_gemm(acc, g_AfH, g_AfL, 12, csH, csL, t0, lane, g, tg);
    __syncthreads();

#pragma unroll
    for (int t = 0; t < 2; t++) {
        int kb = (t0 + t) * 16;
#pragma unroll
        for (int nt = 0; nt < 9; nt++) {
            *(float4*)&qf[(((t0 + t) * 9 + nt) * 32 + lane) * 4] =
                make_float4(acc[t][nt][0], acc[t][nt][1], acc[t][nt][2], acc[t][nt][3]);
#pragma unroll
            for (int e = 0; e < 4; e++) {
                float cv = softthr(acc[t][nt][e] * invL, thr);
                c_reg[t][nt][e] = cv;
                int n = nt * 8 + 2 * tg + (e & 1);
                int m = kb + g + 8 * (e >> 1);
                __half h = __float2half(cv);
                csH[n * CSTR + m] = h;
                csL[n * CSTR + m] = __float2half(cv - __half2float(h));
            }
        }
    }
    __syncthreads();

    // ---- 24 remaining ISTA iterations (direct-LDG operand path) ----
    for (int it = 0; it < 24; it++) {
#pragma unroll
        for (int a = 0; a < 2; a++)
#pragma unroll
            for (int b = 0; b < 9; b++)
#pragma unroll
                for (int e = 0; e < 4; e++) acc[a][b][e] = 0.f;
        frag_gemm(acc, g_XfH, g_XfL, 16, csH, csL, t0, lane, g, tg);
        __syncthreads();
#pragma unroll
        for (int t = 0; t < 2; t++) {
            int kb = (t0 + t) * 16;
#pragma unroll
            for (int nt = 0; nt < 9; nt++) {
                float4 q = *(const float4*)&qf[(((t0 + t) * 9 + nt) * 32 + lane) * 4];
                float qv[4] = {q.x, q.y, q.z, q.w};
#pragma unroll
                for (int e = 0; e < 4; e++) {
                    float cn = softthr(c_reg[t][nt][e] - (acc[t][nt][e] - qv[e]) * invL, thr);
                    c_reg[t][nt][e] = cn;
                    int n = nt * 8 + 2 * tg + (e & 1);
                    int m = kb + g + 8 * (e >> 1);
                    __half h = __float2half(cn);
                    csH[n * CSTR + m] = h;
                    csL[n * CSTR + m] = __float2half(cn - __half2float(h));
                }
            }
        }
        __syncthreads();
    }

    // ---- fused rec = c^T A + mean ----
    {
        const uint4* FH = (const uint4*)g_AtfH;
        const uint4* FL = (const uint4*)g_AtfL;
        float r0a[9][4], r1a[9][4];
#pragma unroll
        for (int b = 0; b < 9; b++)
#pragma unroll
            for (int e = 0; e < 4; e++) { r0a[b][e] = 0.f; r1a[b][e] = 0.f; }
        const int tt0 = w;
        const int tt1 = 8 + w;
        const bool has2 = (w < 4);
        for (int s = 0; s < 16; s++) {
            uint4 ah0 = FH[(s * 12 + tt0) * 32 + lane];
            uint4 al0 = FL[(s * 12 + tt0) * 32 + lane];
            uint4 ah1, al1;
            if (has2) {
                ah1 = FH[(s * 12 + tt1) * 32 + lane];
                al1 = FL[(s * 12 + tt1) * 32 + lane];
            }
            const __half* bh = csH + g * CSTR + s * 16 + 2 * tg;
            const __half* bl = csL + g * CSTR + s * 16 + 2 * tg;
#pragma unroll
            for (int nt = 0; nt < 9; nt++) {
                u32 b0h = *(const u32*)(bh + nt * 8 * CSTR);
                u32 b1h = *(const u32*)(bh + nt * 8 * CSTR + 8);
                u32 b0l = *(const u32*)(bl + nt * 8 * CSTR);
                u32 b1l = *(const u32*)(bl + nt * 8 * CSTR + 8);
                mma16816(r0a[nt], (const u32*)&ah0, b0h, b1h);
                mma16816(r0a[nt], (const u32*)&al0, b0h, b1h);
                mma16816(r0a[nt], (const u32*)&ah0, b0l, b1l);
                if (has2) {
                    mma16816(r1a[nt], (const u32*)&ah1, b0h, b1h);
                    mma16816(r1a[nt], (const u32*)&al1, b0h, b1h);
                    mma16816(r1a[nt], (const u32*)&ah1, b0l, b1l);
                }
            }
        }
#pragma unroll
        for (int nt = 0; nt < 9; nt++)
#pragma unroll
            for (int e = 0; e < 4; e++) {
                int n = nt * 8 + 2 * tg + (e & 1);
                int d = tt0 * 16 + g + 8 * (e >> 1);
                float m = msh[n];
                g_rec[(size_t)(n0 + n) * D_ + d] = r0a[nt][e] + m;
                if (has2) {
                    int d1 = tt1 * 16 + g + 8 * (e >> 1);
                    g_rec[(size_t)(n0 + n) * D_ + d1] = r1a[nt][e] + m;
                }
            }
    }
}

// ---------------- k_out ----------------
__global__ void k_out(float* __restrict__ out) {
    int idx = blockIdx.x * 256 + threadIdx.x;
    if (idx >= 8 * 3 * 256 * 256) return;
    int w = idx & 255, h = (idx >> 8) & 255;
    int ch = (idx >> 16) % 3, b = (idx >> 16) / 3;
    int ihi = h >> 2; if (ihi > 62) ihi = 62;
    int ilo = (h >= 7) ? ((h - 4) >> 2) : 0;
    int jhi = w >> 2; if (jhi > 62) jhi = 62;
    int jlo = (w >= 7) ? ((w - 4) >> 2) : 0;
    float s = 0.f;
    int cnt = 0;
    for (int i = ilo; i <= ihi; i++) {
        int u = h - 4 * i;
        for (int j = jlo; j <= jhi; j++) {
            int v = w - 4 * j;
            int n = b * 3969 + i * 63 + j;
            s += g_rec[(size_t)n * D_ + ch * 64 + u * 8 + v];
            cnt++;
        }
    }
    out[idx] = s / (float)cnt;
}

// ---------------- host launcher ----------------
extern "C" void kernel_launch(void* const* d_in, const int* in_sizes, int n_in,
                              void* d_out, int out_size) {
    const float* y = (const float*)d_in[0];
    const float* atoms = (const float*)d_in[1];
    if (n_in >= 2 && in_sizes[0] < in_sizes[1]) {
        y = (const float*)d_in[1];
        atoms = (const float*)d_in[0];
    }
    float* out = (float*)d_out;

    k_reset<<<1, 32>>>();                          // 0
    k_chain<<<NB, 256>>>(atoms);                   // 1
    k_frag<<<80, 256>>>();                         // 2 (merged X/A/At frags)

    cudaFuncSetAttribute(k_ista, cudaFuncAttributeMaxDynamicSharedMemorySize, SM_ISTA);
    k_ista<<<NCTA, 256, SM_ISTA>>>(y);             // 3 (in sampler window)

    k_out<<<(8 * 3 * 256 * 256 + 255) / 256, 256>>>(out);  // 4
}

// round 15
// speedup vs baseline: 1.8074x; 1.8074x over previous
#include <cuda_runtime.h>
#include <cuda_fp16.h>
#include <math.h>

#define NP   31752
#define D_   192
#define NA   256
#define LMB  0.1f
#define NSQ  9
#define T_   72
#define NCTA 441
#define NB   64
#define CSTR 264                 // cs row stride in halfs

typedef unsigned long long ull;
typedef unsigned int u32;

// ---------------- static device scratch ----------------
__device__ float  g_A[NA * D_];
__device__ float  g_At[D_ * NA];
__device__ float  g_X[NA * NA];
__device__ float  g_Ma[NA * NA];
__device__ float  g_Mb[NA * NA];
__device__ __half g_XfH[16 * 16 * 32 * 8];    // X frags [s16][t16][lane][8]
__device__ __half g_XfL[16 * 16 * 32 * 8];
__device__ __half g_AfH[12 * 16 * 32 * 8];    // dict frags (q-phase) [s12][t16]
__device__ __half g_AfL[12 * 16 * 32 * 8];
__device__ __half g_AtfH[16 * 12 * 32 * 8];   // dict-T frags (rec) [s16][t12]
__device__ __half g_AtfL[16 * 12 * 32 * 8];
__device__ float  g_fs[16];
__device__ float  g_params[4];
__device__ float  g_rec[(size_t)NP * D_];
__device__ unsigned g_arrive = 0;

// ---------------- helpers ----------------
__device__ __forceinline__ float softthr(float v, float thr) {
    float a = fabsf(v) - thr;
    return a > 0.f ? copysignf(a, v) : 0.f;
}
__device__ __forceinline__ void mma16816(float* d, const u32* a, u32 b0, u32 b1) {
    asm volatile(
        "mma.sync.aligned.m16n8k16.row.col.f32.f16.f16.f32 "
        "{%0,%1,%2,%3}, {%4,%5,%6,%7}, {%8,%9}, {%0,%1,%2,%3};"
        : "+f"(d[0]), "+f"(d[1]), "+f"(d[2]), "+f"(d[3])
        : "r"(a[0]), "r"(a[1]), "r"(a[2]), "r"(a[3]), "r"(b0), "r"(b1));
}

// ---------------- k_reset + grid barrier ----------------
__global__ void k_reset() { if (threadIdx.x == 0) g_arrive = 0; }

__device__ __forceinline__ void gsync(unsigned target) {
    __threadfence();
    __syncthreads();
    if (threadIdx.x == 0) {
        atomicAdd(&g_arrive, 1u);
        while (*((volatile unsigned*)&g_arrive) < target) { }
        __threadfence();
    }
    __syncthreads();
}

// ---------------- k_chain (proven): normalize + Gram + spectral norm ----------------
__global__ void __launch_bounds__(256, 1) k_chain(const float* __restrict__ atoms) {
    __shared__ float AshT[NA * 4];
    __shared__ float red[256];
    const int tid = threadIdx.x;
    const int cta = blockIdx.x;
    const int r0 = cta * 4;
    unsigned bar = 0;

    if (cta == 0 && tid < 16) g_fs[tid] = 0.f;
    {
        int r = tid >> 6, l = tid & 63;
        int row = r0 + r;
        float v0 = atoms[row * D_ + l];
        float v1 = atoms[row * D_ + l + 64];
        float v2 = atoms[row * D_ + l + 128];
        red[tid] = v0 * v0 + v1 * v1 + v2 * v2;
        __syncthreads();
        for (int o = 32; o > 0; o >>= 1) {
            if (l < o) red[tid] += red[tid + o];
            __syncthreads();
        }
        float inv = 1.0f / sqrtf(red[r * 64]);
        float a0 = v0 * inv, a1 = v1 * inv, a2 = v2 * inv;
        g_A[row * D_ + l]       = a0;  g_At[l * NA + row]         = a0;
        g_A[row * D_ + l + 64]  = a1;  g_At[(l + 64) * NA + row]  = a1;
        g_A[row * D_ + l + 128] = a2;  g_At[(l + 128) * NA + row] = a2;
    }
    gsync(++bar * NB);

    {
        for (int i = tid; i < 4 * D_; i += 256) {
            int r = i / D_, k = i % D_;
            AshT[k * 4 + r] = g_A[(r0 + r) * D_ + k];
        }
        __syncthreads();
        int c = tid;
        float acc0 = 0.f, acc1 = 0.f, acc2 = 0.f, acc3 = 0.f;
        for (int k = 0; k < D_; k++) {
            float b = __ldcg(&g_At[k * NA + c]);
            float4 a4 = *(const float4*)&AshT[k * 4];
            acc0 += a4.x * b; acc1 += a4.y * b; acc2 += a4.z * b; acc3 += a4.w * b;
        }
        g_X[(r0 + 0) * NA + c] = acc0;
        g_X[(r0 + 1) * NA + c] = acc1;
        g_X[(r0 + 2) * NA + c] = acc2;
        g_X[(r0 + 3) * NA + c] = acc3;
        float fsum = acc0 * acc0 + acc1 * acc1 + acc2 * acc2 + acc3 * acc3;
#pragma unroll
        for (int o = 16; o > 0; o >>= 1) fsum += __shfl_xor_sync(0xffffffffu, fsum, o);
        if ((tid & 31) == 0) atomicAdd(&g_fs[1], fsum);
        __syncthreads();
    }
    gsync(++bar * NB);

    const float* In = g_X;
    float* Out = g_Ma;
    for (int j = 1; j <= NSQ; j++) {
        float scale = 1.0f / __ldcg(&g_fs[j]);
        for (int i = tid; i < 1024; i += 256) {
            int r = i >> 8, k = i & 255;
            AshT[k * 4 + r] = __ldcg(&In[(r0 + r) * NA + k]);
        }
        __syncthreads();
        int c = tid;
        float acc0 = 0.f, acc1 = 0.f, acc2 = 0.f, acc3 = 0.f;
        for (int k = 0; k < NA; k++) {
            float b = __ldcg(&In[k * NA + c]);
            float4 a4 = *(const float4*)&AshT[k * 4];
            acc0 += a4.x * b; acc1 += a4.y * b; acc2 += a4.z * b; acc3 += a4.w * b;
        }
        acc0 *= scale; acc1 *= scale; acc2 *= scale; acc3 *= scale;
        Out[(r0 + 0) * NA + c] = acc0;
        Out[(r0 + 1) * NA + c] = acc1;
        Out[(r0 + 2) * NA + c] = acc2;
        Out[(r0 + 3) * NA + c] = acc3;
        float fsum = acc0 * acc0 + acc1 * acc1 + acc2 * acc2 + acc3 * acc3;
#pragma unroll
        for (int o = 16; o > 0; o >>= 1) fsum += __shfl_xor_sync(0xffffffffu, fsum, o);
        if ((tid & 31) == 0) atomicAdd(&g_fs[j + 1], fsum);
        const float* nIn = Out;
        Out = (Out == g_Ma) ? g_Mb : g_Ma;
        In = nIn;
        gsync(++bar * NB);
    }

    if (cta == 0) {
        red[tid] = __ldcg(&In[tid * NA + tid]);
        __syncthreads();
        for (int o = 128; o > 0; o >>= 1) {
            if (tid < o) red[tid] += red[tid + o];
            __syncthreads();
        }
        if (tid == 0) {
            double lg = log((double)red[0]);
            for (int j = 1; j <= NSQ; j++)
                lg += (double)(1 << (NSQ - j)) * log((double)__ldcg(&g_fs[j]));
            double L = exp(lg / (double)(1 << NSQ));
            g_params[0] = (float)L;
            g_params[1] = (float)(1.0 / L);
            g_params[2] = (float)((double)LMB / L);
        }
    }
}

// ---------------- merged fragment pre-swizzle (one launch) ----------------
__device__ __forceinline__ void frag_core(__half* dH, __half* dL,
                                          const float* __restrict__ src, int stride,
                                          int s, int t, int lane, size_t sidx) {
    int g = lane >> 2, tg = lane & 3;
    int r = t * 16 + g, k = s * 16 + 2 * tg;
    float v[8];
    v[0] = src[r * stride + k];           v[1] = src[r * stride + k + 1];
    v[2] = src[(r + 8) * stride + k];     v[3] = src[(r + 8) * stride + k + 1];
    v[4] = src[r * stride + k + 8];       v[5] = src[r * stride + k + 9];
    v[6] = src[(r + 8) * stride + k + 8]; v[7] = src[(r + 8) * stride + k + 9];
    u32 ph[4], pl[4];
#pragma unroll
    for (int i = 0; i < 4; i++) {
        __half h0 = __float2half(v[2 * i]);
        __half h1 = __float2half(v[2 * i + 1]);
        __half l0 = __float2half(v[2 * i] - __half2float(h0));
        __half l1 = __float2half(v[2 * i + 1] - __half2float(h1));
        __half2 hh = __halves2half2(h0, h1);
        __half2 ll = __halves2half2(l0, l1);
        ph[i] = *(u32*)&hh; pl[i] = *(u32*)&ll;
    }
    *(uint4*)&dH[sidx * 8] = make_uint4(ph[0], ph[1], ph[2], ph[3]);
    *(uint4*)&dL[sidx * 8] = make_uint4(pl[0], pl[1], pl[2], pl[3]);
}

// blocks 0..31: X (8192 items); 32..55: A (6144); 56..79: At (6144)
__global__ void k_frag() {
    int blk = blockIdx.x;
    if (blk < 32) {
        int id = blk * 256 + threadIdx.x;
        if (id >= 16 * 16 * 32) return;
        int lane = id & 31, t = (id >> 5) & 15, s = id >> 9;
        frag_core(g_XfH, g_XfL, g_X, NA, s, t, lane, (size_t)(s * 16 + t) * 32 + lane);
    } else if (blk < 56) {
        int id = (blk - 32) * 256 + threadIdx.x;
        if (id >= 12 * 16 * 32) return;
        int lane = id & 31, t = (id >> 5) & 15, s = id >> 9;
        frag_core(g_AfH, g_AfL, g_A, D_, s, t, lane, (size_t)(s * 16 + t) * 32 + lane);
    } else {
        int id = (blk - 56) * 256 + threadIdx.x;
        if (id >= 16 * 12 * 32) return;
        int lane = id & 31, rest = id >> 5;
        int t = rest % 12, s = rest / 12;
        frag_core(g_AtfH, g_AtfL, g_At, NA, s, t, lane, (size_t)(s * 12 + t) * 32 + lane);
    }
}

// ---------------- k_ista: 16-warp HMMA split ISTA ----------------
// SMEM: csH 38016 | csL 38016 | qf 73728 | msh 288  -> 150048 bytes
#define CSH_OFF 0
#define CSL_OFF 38016
#define QF_OFF  76032
#define MSH_OFF 149760
#define SM_ISTA 150048

// one m-tile per warp: acc[9][4] += frag-GEMM over nks k-chunks
__device__ __forceinline__ void frag_gemm1(float (&acc)[9][4],
                                           const __half* __restrict__ fH,
                                           const __half* __restrict__ fL,
                                           int nks, int ntiles,
                                           const __half* csH, const __half* csL,
                                           int mt, int lane, int g, int tg) {
    const uint4* FH = (const uint4*)fH;
    const uint4* FL = (const uint4*)fL;
    uint4 ah = FH[(0 * ntiles + mt) * 32 + lane];
    uint4 al = FL[(0 * ntiles + mt) * 32 + lane];
    for (int s = 0; s < nks; s++) {
        uint4 nh, nl;
        if (s + 1 < nks) {
            nh = FH[((s + 1) * ntiles + mt) * 32 + lane];
            nl = FL[((s + 1) * ntiles + mt) * 32 + lane];
        }
        const __half* bh = csH + g * CSTR + s * 16 + 2 * tg;
        const __half* bl = csL + g * CSTR + s * 16 + 2 * tg;
#pragma unroll
        for (int nt = 0; nt < 9; nt++) {
            u32 b0h = *(const u32*)(bh + nt * 8 * CSTR);
            u32 b1h = *(const u32*)(bh + nt * 8 * CSTR + 8);
            u32 b0l = *(const u32*)(bl + nt * 8 * CSTR);
            u32 b1l = *(const u32*)(bl + nt * 8 * CSTR + 8);
            mma16816(acc[nt], (const u32*)&ah, b0h, b1h);
            mma16816(acc[nt], (const u32*)&al, b0h, b1h);
            mma16816(acc[nt], (const u32*)&ah, b0l, b1l);
        }
        ah = nh; al = nl;
    }
}

__global__ void __launch_bounds__(512, 1) k_ista(const float* __restrict__ y) {
    extern __shared__ char smb[];
    __half* csH = (__half*)(smb + CSH_OFF);
    __half* csL = (__half*)(smb + CSL_OFF);
    float* qf = (float*)(smb + QF_OFF);
    float* msh = (float*)(smb + MSH_OFF);
    const int tid = threadIdx.x;
    const int w = tid >> 5, lane = tid & 31, g = lane >> 2, tg = lane & 3;
    const int n0 = blockIdx.x * T_;
    const float invL = g_params[1], thr = g_params[2];

    // ---- fused per-patch mean (warps 0..7, 9 patches each) ----
    if (w < 8) {
        for (int i = 0; i < 9; i++) {
            int j = w * 9 + i;
            int n = n0 + j;
            int b = n / 3969, r = n % 3969, pi = r / 63, pj = r % 63;
            float s = 0.f;
#pragma unroll
            for (int dd = 0; dd < 6; dd++) {
                int d = lane * 6 + dd;
                int ch = d >> 6, u = (d >> 3) & 7, v = d & 7;
                s += y[((b * 3 + ch) * 256 + pi * 4 + u) * 256 + pj * 4 + v];
            }
#pragma unroll
            for (int o = 16; o > 0; o >>= 1) s += __shfl_xor_sync(0xffffffffu, s, o);
            if (lane == 0) msh[j] = s * (1.f / 192.f);
        }
    }
    __syncthreads();

    // ---- gather centered patches ----
    for (int e = tid; e < 72 * 192; e += 512) {
        int j = e / 192, d = e % 192;
        int n = n0 + j;
        int b = n / 3969, r = n % 3969, pi = r / 63, pj = r % 63;
        int ch = d >> 6, u = (d >> 3) & 7, v = d & 7;
        float pv = y[((b * 3 + ch) * 256 + pi * 4 + u) * 256 + pj * 4 + v] - msh[j];
        __half h = __float2half(pv);
        csH[j * CSTR + d] = h;
        csL[j * CSTR + d] = __float2half(pv - __half2float(h));
    }
    __syncthreads();

    float acc[9][4];
    float c_reg[9][4];
#pragma unroll
    for (int b = 0; b < 9; b++)
#pragma unroll
        for (int e = 0; e < 4; e++) acc[b][e] = 0.f;

    // ---- q = A @ p^T : 12 k-chunks, m-tile = w ----
    frag_gemm1(acc, g_AfH, g_AfL, 12, 16, csH, csL, w, lane, g, tg);
    __syncthreads();   // all B reads done before cs overwritten

    {
        int kb = w * 16;
#pragma unroll
        for (int nt = 0; nt < 9; nt++) {
            *(float4*)&qf[((w * 9 + nt) * 32 + lane) * 4] =
                make_float4(acc[nt][0], acc[nt][1], acc[nt][2], acc[nt][3]);
#pragma unroll
            for (int e = 0; e < 4; e++) {
                float cv = softthr(acc[nt][e] * invL, thr);
                c_reg[nt][e] = cv;
                int n = nt * 8 + 2 * tg + (e & 1);
                int m = kb + g + 8 * (e >> 1);
                __half h = __float2half(cv);
                csH[n * CSTR + m] = h;
                csL[n * CSTR + m] = __float2half(cv - __half2float(h));
            }
        }
    }
    __syncthreads();

    // ---- 24 remaining ISTA iterations ----
    for (int it = 0; it < 24; it++) {
#pragma unroll
        for (int b = 0; b < 9; b++)
#pragma unroll
            for (int e = 0; e < 4; e++) acc[b][e] = 0.f;
        frag_gemm1(acc, g_XfH, g_XfL, 16, 16, csH, csL, w, lane, g, tg);
        __syncthreads();   // all warps done reading cs
        int kb = w * 16;
#pragma unroll
        for (int nt = 0; nt < 9; nt++) {
            float4 q = *(const float4*)&qf[((w * 9 + nt) * 32 + lane) * 4];
            float qv[4] = {q.x, q.y, q.z, q.w};
#pragma unroll
            for (int e = 0; e < 4; e++) {
                float cn = softthr(c_reg[nt][e] - (acc[nt][e] - qv[e]) * invL, thr);
                c_reg[nt][e] = cn;
                int n = nt * 8 + 2 * tg + (e & 1);
                int m = kb + g + 8 * (e >> 1);
                __half h = __float2half(cn);
                csH[n * CSTR + m] = h;
                csL[n * CSTR + m] = __float2half(cn - __half2float(h));
            }
        }
        __syncthreads();
    }

    // ---- fused rec = c^T A + mean : warps 0..11, d-tile = w ----
    if (w < 12) {
        float racc[9][4];
#pragma unroll
        for (int b = 0; b < 9; b++)
#pragma unroll
            for (int e = 0; e < 4; e++) racc[b][e] = 0.f;
        frag_gemm1(racc, g_AtfH, g_AtfL, 16, 12, csH, csL, w, lane, g, tg);
#pragma unroll
        for (int nt = 0; nt < 9; nt++)
#pragma unroll
            for (int e = 0; e < 4; e++) {
                int n = nt * 8 + 2 * tg + (e & 1);
                int d = w * 16 + g + 8 * (e >> 1);
                g_rec[(size_t)(n0 + n) * D_ + d] = racc[nt][e] + msh[n];
            }
    }
}

// ---------------- k_out ----------------
__global__ void k_out(float* __restrict__ out) {
    int idx = blockIdx.x * 256 + threadIdx.x;
    if (idx >= 8 * 3 * 256 * 256) return;
    int w = idx & 255, h = (idx >> 8) & 255;
    int ch = (idx >> 16) % 3, b = (idx >> 16) / 3;
    int ihi = h >> 2; if (ihi > 62) ihi = 62;
    int ilo = (h >= 7) ? ((h - 4) >> 2) : 0;
    int jhi = w >> 2; if (jhi > 62) jhi = 62;
    int jlo = (w >= 7) ? ((w - 4) >> 2) : 0;
    float s = 0.f;
    int cnt = 0;
    for (int i = ilo; i <= ihi; i++) {
        int u = h - 4 * i;
        for (int j = jlo; j <= jhi; j++) {
            int v = w - 4 * j;
            int n = b * 3969 + i * 63 + j;
            s += g_rec[(size_t)n * D_ + ch * 64 + u * 8 + v];
            cnt++;
        }
    }
    out[idx] = s / (float)cnt;
}

// ---------------- host launcher ----------------
extern "C" void kernel_launch(void* const* d_in, const int* in_sizes, int n_in,
                              void* d_out, int out_size) {
    const float* y = (const float*)d_in[0];
    const float* atoms = (const float*)d_in[1];
    if (n_in >= 2 && in_sizes[0] < in_sizes[1]) {
        y = (const float*)d_in[1];
        atoms = (const float*)d_in[0];
    }
    float* out = (float*)d_out;

    k_reset<<<1, 32>>>();                          // 0
    k_chain<<<NB, 256>>>(atoms);                   // 1
    k_frag<<<80, 256>>>();                         // 2

    cudaFuncSetAttribute(k_ista, cudaFuncAttributeMaxDynamicSharedMemorySize, SM_ISTA);
    k_ista<<<NCTA, 512, SM_ISTA>>>(y);             // 3

    k_out<<<(8 * 3 * 256 * 256 + 255) / 256, 256>>>(out);  // 4
}

// round 16
// speedup vs baseline: 1.9400x; 1.0733x over previous
#include <cuda_runtime.h>
#include <cuda_fp16.h>
#include <math.h>

#define NP   31752
#define D_   192
#define NA   256
#define LMB  0.1f
#define NSQ  9
#define T_   72
#define NCTA 441
#define NB   64
#define CSTR 264                 // cs row stride in halfs
#define CROWB (CSTR * 2)         // cs row stride in bytes

typedef unsigned long long ull;
typedef unsigned int u32;

// ---------------- static device scratch ----------------
__device__ float  g_A[NA * D_];
__device__ float  g_At[D_ * NA];
__device__ float  g_X[NA * NA];
__device__ float  g_Ma[NA * NA];
__device__ float  g_Mb[NA * NA];
__device__ __half g_XfH[16 * 16 * 32 * 8];    // X frags [s16][t16][lane][8]
__device__ __half g_XfL[16 * 16 * 32 * 8];
__device__ __half g_AfH[12 * 16 * 32 * 8];    // dict frags (q-phase) [s12][t16]
__device__ __half g_AfL[12 * 16 * 32 * 8];
__device__ __half g_AtfH[16 * 12 * 32 * 8];   // dict-T frags (rec) [s16][t12]
__device__ __half g_AtfL[16 * 12 * 32 * 8];
__device__ float  g_fs[16];
__device__ float  g_params[4];
__device__ float  g_rec[(size_t)NP * D_];
__device__ unsigned g_arrive = 0;

// ---------------- helpers ----------------
__device__ __forceinline__ float softthr(float v, float thr) {
    float a = fabsf(v) - thr;
    return a > 0.f ? copysignf(a, v) : 0.f;
}
__device__ __forceinline__ void mma16816(float* d, const u32* a, u32 b0, u32 b1) {
    asm volatile(
        "mma.sync.aligned.m16n8k16.row.col.f32.f16.f16.f32 "
        "{%0,%1,%2,%3}, {%4,%5,%6,%7}, {%8,%9}, {%0,%1,%2,%3};"
        : "+f"(d[0]), "+f"(d[1]), "+f"(d[2]), "+f"(d[3])
        : "r"(a[0]), "r"(a[1]), "r"(a[2]), "r"(a[3]), "r"(b0), "r"(b1));
}
__device__ __forceinline__ u32 smem_u32(const void* p) {
    u32 a; asm("{ .reg .u64 t; cvta.to.shared.u64 t, %1; cvt.u32.u64 %0, t; }" : "=r"(a) : "l"(p));
    return a;
}
__device__ __forceinline__ void ldsm_x4(u32& r0, u32& r1, u32& r2, u32& r3, u32 addr) {
    asm volatile("ldmatrix.sync.aligned.m8n8.x4.shared.b16 {%0,%1,%2,%3}, [%4];"
                 : "=r"(r0), "=r"(r1), "=r"(r2), "=r"(r3) : "r"(addr));
}
__device__ __forceinline__ void ldsm_x2(u32& r0, u32& r1, u32 addr) {
    asm volatile("ldmatrix.sync.aligned.m8n8.x2.shared.b16 {%0,%1}, [%2];"
                 : "=r"(r0), "=r"(r1) : "r"(addr));
}
__device__ __forceinline__ void stsm_x4t(u32 addr, u32 r0, u32 r1, u32 r2, u32 r3) {
    asm volatile("stmatrix.sync.aligned.m8n8.x4.trans.shared.b16 [%0], {%1,%2,%3,%4};"
                 :: "r"(addr), "r"(r0), "r"(r1), "r"(r2), "r"(r3) : "memory");
}
__device__ __forceinline__ void stsm_x2t(u32 addr, u32 r0, u32 r1) {
    asm volatile("stmatrix.sync.aligned.m8n8.x2.trans.shared.b16 [%0], {%1,%2};"
                 :: "r"(addr), "r"(r0), "r"(r1) : "memory");
}
__device__ __forceinline__ u32 packh2(float a, float b) {
    __half2 h = __halves2half2(__float2half(a), __float2half(b));
    return *(u32*)&h;
}

// ---------------- k_reset + grid barrier ----------------
__global__ void k_reset() { if (threadIdx.x == 0) g_arrive = 0; }

__device__ __forceinline__ void gsync(unsigned target) {
    __threadfence();
    __syncthreads();
    if (threadIdx.x == 0) {
        atomicAdd(&g_arrive, 1u);
        while (*((volatile unsigned*)&g_arrive) < target) { }
        __threadfence();
    }
    __syncthreads();
}

// ---------------- k_chain (proven): normalize + Gram + spectral norm ----------------
__global__ void __launch_bounds__(256, 1) k_chain(const float* __restrict__ atoms) {
    __shared__ float AshT[NA * 4];
    __shared__ float red[256];
    const int tid = threadIdx.x;
    const int cta = blockIdx.x;
    const int r0 = cta * 4;
    unsigned bar = 0;

    if (cta == 0 && tid < 16) g_fs[tid] = 0.f;
    {
        int r = tid >> 6, l = tid & 63;
        int row = r0 + r;
        float v0 = atoms[row * D_ + l];
        float v1 = atoms[row * D_ + l + 64];
        float v2 = atoms[row * D_ + l + 128];
        red[tid] = v0 * v0 + v1 * v1 + v2 * v2;
        __syncthreads();
        for (int o = 32; o > 0; o >>= 1) {
            if (l < o) red[tid] += red[tid + o];
            __syncthreads();
        }
        float inv = 1.0f / sqrtf(red[r * 64]);
        float a0 = v0 * inv, a1 = v1 * inv, a2 = v2 * inv;
        g_A[row * D_ + l]       = a0;  g_At[l * NA + row]         = a0;
        g_A[row * D_ + l + 64]  = a1;  g_At[(l + 64) * NA + row]  = a1;
        g_A[row * D_ + l + 128] = a2;  g_At[(l + 128) * NA + row] = a2;
    }
    gsync(++bar * NB);

    {
        for (int i = tid; i < 4 * D_; i += 256) {
            int r = i / D_, k = i % D_;
            AshT[k * 4 + r] = g_A[(r0 + r) * D_ + k];
        }
        __syncthreads();
        int c = tid;
        float acc0 = 0.f, acc1 = 0.f, acc2 = 0.f, acc3 = 0.f;
        for (int k = 0; k < D_; k++) {
            float b = __ldcg(&g_At[k * NA + c]);
            float4 a4 = *(const float4*)&AshT[k * 4];
            acc0 += a4.x * b; acc1 += a4.y * b; acc2 += a4.z * b; acc3 += a4.w * b;
        }
        g_X[(r0 + 0) * NA + c] = acc0;
        g_X[(r0 + 1) * NA + c] = acc1;
        g_X[(r0 + 2) * NA + c] = acc2;
        g_X[(r0 + 3) * NA + c] = acc3;
        float fsum = acc0 * acc0 + acc1 * acc1 + acc2 * acc2 + acc3 * acc3;
#pragma unroll
        for (int o = 16; o > 0; o >>= 1) fsum += __shfl_xor_sync(0xffffffffu, fsum, o);
        if ((tid & 31) == 0) atomicAdd(&g_fs[1], fsum);
        __syncthreads();
    }
    gsync(++bar * NB);

    const float* In = g_X;
    float* Out = g_Ma;
    for (int j = 1; j <= NSQ; j++) {
        float scale = 1.0f / __ldcg(&g_fs[j]);
        for (int i = tid; i < 1024; i += 256) {
            int r = i >> 8, k = i & 255;
            AshT[k * 4 + r] = __ldcg(&In[(r0 + r) * NA + k]);
        }
        __syncthreads();
        int c = tid;
        float acc0 = 0.f, acc1 = 0.f, acc2 = 0.f, acc3 = 0.f;
        for (int k = 0; k < NA; k++) {
            float b = __ldcg(&In[k * NA + c]);
            float4 a4 = *(const float4*)&AshT[k * 4];
            acc0 += a4.x * b; acc1 += a4.y * b; acc2 += a4.z * b; acc3 += a4.w * b;
        }
        acc0 *= scale; acc1 *= scale; acc2 *= scale; acc3 *= scale;
        Out[(r0 + 0) * NA + c] = acc0;
        Out[(r0 + 1) * NA + c] = acc1;
        Out[(r0 + 2) * NA + c] = acc2;
        Out[(r0 + 3) * NA + c] = acc3;
        float fsum = acc0 * acc0 + acc1 * acc1 + acc2 * acc2 + acc3 * acc3;
#pragma unroll
        for (int o = 16; o > 0; o >>= 1) fsum += __shfl_xor_sync(0xffffffffu, fsum, o);
        if ((tid & 31) == 0) atomicAdd(&g_fs[j + 1], fsum);
        const float* nIn = Out;
        Out = (Out == g_Ma) ? g_Mb : g_Ma;
        In = nIn;
        gsync(++bar * NB);
    }

    if (cta == 0) {
        red[tid] = __ldcg(&In[tid * NA + tid]);
        __syncthreads();
        for (int o = 128; o > 0; o >>= 1) {
            if (tid < o) red[tid] += red[tid + o];
            __syncthreads();
        }
        if (tid == 0) {
            double lg = log((double)red[0]);
            for (int j = 1; j <= NSQ; j++)
                lg += (double)(1 << (NSQ - j)) * log((double)__ldcg(&g_fs[j]));
            double L = exp(lg / (double)(1 << NSQ));
            g_params[0] = (float)L;
            g_params[1] = (float)(1.0 / L);
            g_params[2] = (float)((double)LMB / L);
        }
    }
}

// ---------------- merged fragment pre-swizzle ----------------
__device__ __forceinline__ void frag_core(__half* dH, __half* dL,
                                          const float* __restrict__ src, int stride,
                                          int s, int t, int lane, size_t sidx) {
    int g = lane >> 2, tg = lane & 3;
    int r = t * 16 + g, k = s * 16 + 2 * tg;
    float v[8];
    v[0] = src[r * stride + k];           v[1] = src[r * stride + k + 1];
    v[2] = src[(r + 8) * stride + k];     v[3] = src[(r + 8) * stride + k + 1];
    v[4] = src[r * stride + k + 8];       v[5] = src[r * stride + k + 9];
    v[6] = src[(r + 8) * stride + k + 8]; v[7] = src[(r + 8) * stride + k + 9];
    u32 ph[4], pl[4];
#pragma unroll
    for (int i = 0; i < 4; i++) {
        __half h0 = __float2half(v[2 * i]);
        __half h1 = __float2half(v[2 * i + 1]);
        __half l0 = __float2half(v[2 * i] - __half2float(h0));
        __half l1 = __float2half(v[2 * i + 1] - __half2float(h1));
        __half2 hh = __halves2half2(h0, h1);
        __half2 ll = __halves2half2(l0, l1);
        ph[i] = *(u32*)&hh; pl[i] = *(u32*)&ll;
    }
    *(uint4*)&dH[sidx * 8] = make_uint4(ph[0], ph[1], ph[2], ph[3]);
    *(uint4*)&dL[sidx * 8] = make_uint4(pl[0], pl[1], pl[2], pl[3]);
}

__global__ void k_frag() {
    int blk = blockIdx.x;
    if (blk < 32) {
        int id = blk * 256 + threadIdx.x;
        if (id >= 16 * 16 * 32) return;
        int lane = id & 31, t = (id >> 5) & 15, s = id >> 9;
        frag_core(g_XfH, g_XfL, g_X, NA, s, t, lane, (size_t)(s * 16 + t) * 32 + lane);
    } else if (blk < 56) {
        int id = (blk - 32) * 256 + threadIdx.x;
        if (id >= 12 * 16 * 32) return;
        int lane = id & 31, t = (id >> 5) & 15, s = id >> 9;
        frag_core(g_AfH, g_AfL, g_A, D_, s, t, lane, (size_t)(s * 16 + t) * 32 + lane);
    } else {
        int id = (blk - 56) * 256 + threadIdx.x;
        if (id >= 16 * 12 * 32) return;
        int lane = id & 31, rest = id >> 5;
        int t = rest % 12, s = rest / 12;
        frag_core(g_AtfH, g_AtfL, g_At, NA, s, t, lane, (size_t)(s * 12 + t) * 32 + lane);
    }
}

// ---------------- k_ista: 16-warp HMMA + ldmatrix/stmatrix ----------------
// SMEM: csH 38016 | csL 38016 | qf 73728 | msh 288  -> 150048 bytes
#define CSH_OFF 0
#define CSL_OFF 38016
#define QF_OFF  76032
#define MSH_OFF 149760
#define SM_ISTA 150048

// one m-tile per warp; B via ldmatrix. laneOff = per-lane x4 address offset (pair 0),
// laneOff2 = per-lane x2 offset (tile 8).
__device__ __forceinline__ void frag_gemm1(float (&acc)[9][4],
                                           const __half* __restrict__ fH,
                                           const __half* __restrict__ fL,
                                           int nks, int ntiles,
                                           u32 csHu, u32 csLu, u32 laneOff, u32 laneOff2,
                                           int mt, int lane) {
    const uint4* FH = (const uint4*)fH;
    const uint4* FL = (const uint4*)fL;
    uint4 ah = FH[(0 * ntiles + mt) * 32 + lane];
    uint4 al = FL[(0 * ntiles + mt) * 32 + lane];
    for (int s = 0; s < nks; s++) {
        uint4 nh, nl;
        if (s + 1 < nks) {
            nh = FH[((s + 1) * ntiles + mt) * 32 + lane];
            nl = FL[((s + 1) * ntiles + mt) * 32 + lane];
        }
        u32 kadd = (u32)s * 32;
#pragma unroll
        for (int p = 0; p < 4; p++) {
            u32 rh0, rh1, rh2, rh3, rl0, rl1, rl2, rl3;
            u32 aH = csHu + laneOff + (u32)p * (16 * CROWB) + kadd;
            u32 aL = csLu + laneOff + (u32)p * (16 * CROWB) + kadd;
            ldsm_x4(rh0, rh1, rh2, rh3, aH);
            ldsm_x4(rl0, rl1, rl2, rl3, aL);
            mma16816(acc[2 * p],     (const u32*)&ah, rh0, rh1);
            mma16816(acc[2 * p],     (const u32*)&al, rh0, rh1);
            mma16816(acc[2 * p],     (const u32*)&ah, rl0, rl1);
            mma16816(acc[2 * p + 1], (const u32*)&ah, rh2, rh3);
            mma16816(acc[2 * p + 1], (const u32*)&al, rh2, rh3);
            mma16816(acc[2 * p + 1], (const u32*)&ah, rl2, rl3);
        }
        {
            u32 rh0, rh1, rl0, rl1;
            ldsm_x2(rh0, rh1, csHu + laneOff2 + kadd);
            ldsm_x2(rl0, rl1, csLu + laneOff2 + kadd);
            mma16816(acc[8], (const u32*)&ah, rh0, rh1);
            mma16816(acc[8], (const u32*)&al, rh0, rh1);
            mma16816(acc[8], (const u32*)&ah, rl0, rl1);
        }
        ah = nh; al = nl;
    }
}

// store c (hi/lo) for all 9 tiles of this warp's k-columns via stmatrix.trans
__device__ __forceinline__ void store_c(const float (&c_reg)[9][4],
                                        u32 csHu, u32 csLu, u32 laneOff, u32 laneOff2,
                                        int w) {
    u32 kadd = (u32)w * 32;
#pragma unroll
    for (int p = 0; p < 4; p++) {
        int n0t = 2 * p, n1t = 2 * p + 1;
        u32 h0 = packh2(c_reg[n0t][0], c_reg[n0t][1]);
        u32 h1 = packh2(c_reg[n0t][2], c_reg[n0t][3]);
        u32 h2 = packh2(c_reg[n1t][0], c_reg[n1t][1]);
        u32 h3 = packh2(c_reg[n1t][2], c_reg[n1t][3]);
        __half2* hp;
        float l00, l01, l02, l03;
        hp = (__half2*)&h0; l00 = c_reg[n0t][0] - __half2float(__low2half(*hp));
        l01 = c_reg[n0t][1] - __half2float(__high2half(*hp));
        hp = (__half2*)&h1; l02 = c_reg[n0t][2] - __half2float(__low2half(*hp));
        l03 = c_reg[n0t][3] - __half2float(__high2half(*hp));
        u32 L0 = packh2(l00, l01), L1 = packh2(l02, l03);
        hp = (__half2*)&h2; l00 = c_reg[n1t][0] - __half2float(__low2half(*hp));
        l01 = c_reg[n1t][1] - __half2float(__high2half(*hp));
        hp = (__half2*)&h3; l02 = c_reg[n1t][2] - __half2float(__low2half(*hp));
        l03 = c_reg[n1t][3] - __half2float(__high2half(*hp));
        u32 L2 = packh2(l00, l01), L3 = packh2(l02, l03);
        stsm_x4t(csHu + laneOff + (u32)p * (16 * CROWB) + kadd, h0, h1, h2, h3);
        stsm_x4t(csLu + laneOff + (u32)p * (16 * CROWB) + kadd, L0, L1, L2, L3);
    }
    {
        u32 h0 = packh2(c_reg[8][0], c_reg[8][1]);
        u32 h1 = packh2(c_reg[8][2], c_reg[8][3]);
        __half2* hp;
        hp = (__half2*)&h0;
        float l0 = c_reg[8][0] - __half2float(__low2half(*hp));
        float l1 = c_reg[8][1] - __half2float(__high2half(*hp));
        hp = (__half2*)&h1;
        float l2 = c_reg[8][2] - __half2float(__low2half(*hp));
        float l3 = c_reg[8][3] - __half2float(__high2half(*hp));
        stsm_x2t(csHu + laneOff2 + kadd, h0, h1);
        stsm_x2t(csLu + laneOff2 + kadd, packh2(l0, l1), packh2(l2, l3));
    }
}

__global__ void __launch_bounds__(512, 1) k_ista(const float* __restrict__ y) {
    extern __shared__ char smb[];
    __half* csH = (__half*)(smb + CSH_OFF);
    __half* csL = (__half*)(smb + CSL_OFF);
    float* qf = (float*)(smb + QF_OFF);
    float* msh = (float*)(smb + MSH_OFF);
    const int tid = threadIdx.x;
    const int w = tid >> 5, lane = tid & 31, g = lane >> 2, tg = lane & 3;
    const int n0 = blockIdx.x * T_;
    const float invL = g_params[1], thr = g_params[2];
    const u32 csHu = smem_u32(csH);
    const u32 csLu = smem_u32(csL);
    // ldmatrix/stmatrix per-lane address offsets
    const int mm = lane >> 3;
    const u32 laneOff = (u32)((((mm >> 1) & 1) * 8 + (lane & 7)) * CROWB + (mm & 1) * 16);
    const u32 laneOff2 = (u32)((64 + (lane & 7)) * CROWB + ((lane >> 3) & 1) * 16);

    // ---- fused per-patch mean (warps 0..7) ----
    if (w < 8) {
        for (int i = 0; i < 9; i++) {
            int j = w * 9 + i;
            int n = n0 + j;
            int b = n / 3969, r = n % 3969, pi = r / 63, pj = r % 63;
            float s = 0.f;
#pragma unroll
            for (int dd = 0; dd < 6; dd++) {
                int d = lane * 6 + dd;
                int ch = d >> 6, u = (d >> 3) & 7, v = d & 7;
                s += y[((b * 3 + ch) * 256 + pi * 4 + u) * 256 + pj * 4 + v];
            }
#pragma unroll
            for (int o = 16; o > 0; o >>= 1) s += __shfl_xor_sync(0xffffffffu, s, o);
            if (lane == 0) msh[j] = s * (1.f / 192.f);
        }
    }
    __syncthreads();

    // ---- gather centered patches ----
    for (int e = tid; e < 72 * 192; e += 512) {
        int j = e / 192, d = e % 192;
        int n = n0 + j;
        int b = n / 3969, r = n % 3969, pi = r / 63, pj = r % 63;
        int ch = d >> 6, u = (d >> 3) & 7, v = d & 7;
        float pv = y[((b * 3 + ch) * 256 + pi * 4 + u) * 256 + pj * 4 + v] - msh[j];
        __half h = __float2half(pv);
        csH[j * CSTR + d] = h;
        csL[j * CSTR + d] = __float2half(pv - __half2float(h));
    }
    __syncthreads();

    float acc[9][4];
    float c_reg[9][4];
#pragma unroll
    for (int b = 0; b < 9; b++)
#pragma unroll
        for (int e = 0; e < 4; e++) acc[b][e] = 0.f;

    // ---- q = A @ p^T : 12 k-chunks ----
    frag_gemm1(acc, g_AfH, g_AfL, 12, 16, csHu, csLu, laneOff, laneOff2, w, lane);
    __syncthreads();

#pragma unroll
    for (int nt = 0; nt < 9; nt++) {
        *(float4*)&qf[((w * 9 + nt) * 32 + lane) * 4] =
            make_float4(acc[nt][0], acc[nt][1], acc[nt][2], acc[nt][3]);
#pragma unroll
        for (int e = 0; e < 4; e++)
            c_reg[nt][e] = softthr(acc[nt][e] * invL, thr);
    }
    store_c(c_reg, csHu, csLu, laneOff, laneOff2, w);
    __syncthreads();

    // ---- 24 remaining ISTA iterations ----
    for (int it = 0; it < 24; it++) {
#pragma unroll
        for (int b = 0; b < 9; b++)
#pragma unroll
            for (int e = 0; e < 4; e++) acc[b][e] = 0.f;
        frag_gemm1(acc, g_XfH, g_XfL, 16, 16, csHu, csLu, laneOff, laneOff2, w, lane);
        __syncthreads();
#pragma unroll
        for (int nt = 0; nt < 9; nt++) {
            float4 q = *(const float4*)&qf[((w * 9 + nt) * 32 + lane) * 4];
            float qv[4] = {q.x, q.y, q.z, q.w};
#pragma unroll
            for (int e = 0; e < 4; e++)
                c_reg[nt][e] = softthr(c_reg[nt][e] - (acc[nt][e] - qv[e]) * invL, thr);
        }
        store_c(c_reg, csHu, csLu, laneOff, laneOff2, w);
        __syncthreads();
    }

    // ---- fused rec = c^T A + mean : warps 0..11 ----
    if (w < 12) {
        float racc[9][4];
#pragma unroll
        for (int b = 0; b < 9; b++)
#pragma unroll
            for (int e = 0; e < 4; e++) racc[b][e] = 0.f;
        frag_gemm1(racc, g_AtfH, g_AtfL, 16, 12, csHu, csLu, laneOff, laneOff2, w, lane);
#pragma unroll
        for (int nt = 0; nt < 9; nt++)
#pragma unroll
            for (int e = 0; e < 4; e++) {
                int n = nt * 8 + 2 * tg + (e & 1);
                int d = w * 16 + g + 8 * (e >> 1);
                g_rec[(size_t)(n0 + n) * D_ + d] = racc[nt][e] + msh[n];
            }
    }
}

// ---------------- k_out ----------------
__global__ void k_out(float* __restrict__ out) {
    int idx = blockIdx.x * 256 + threadIdx.x;
    if (idx >= 8 * 3 * 256 * 256) return;
    int w = idx & 255, h = (idx >> 8) & 255;
    int ch = (idx >> 16) % 3, b = (idx >> 16) / 3;
    int ihi = h >> 2; if (ihi > 62) ihi = 62;
    int ilo = (h >= 7) ? ((h - 4) >> 2) : 0;
    int jhi = w >> 2; if (jhi > 62) jhi = 62;
    int jlo = (w >= 7) ? ((w - 4) >> 2) : 0;
    float s = 0.f;
    int cnt = 0;
    for (int i = ilo; i <= ihi; i++) {
        int u = h - 4 * i;
        for (int j = jlo; j <= jhi; j++) {
            int v = w - 4 * j;
            int n = b * 3969 + i * 63 + j;
            s += g_rec[(size_t)n * D_ + ch * 64 + u * 8 + v];
            cnt++;
        }
    }
    out[idx] = s / (float)cnt;
}

// ---------------- host launcher ----------------
extern "C" void kernel_launch(void* const* d_in, const int* in_sizes, int n_in,
                              void* d_out, int out_size) {
    const float* y = (const float*)d_in[0];
    const float* atoms = (const float*)d_in[1];
    if (n_in >= 2 && in_sizes[0] < in_sizes[1]) {
        y = (const float*)d_in[1];
        atoms = (const float*)d_in[0];
    }
    float* out = (float*)d_out;

    k_reset<<<1, 32>>>();                          // 0
    k_chain<<<NB, 256>>>(atoms);                   // 1
    k_frag<<<80, 256>>>();                         // 2

    cudaFuncSetAttribute(k_ista, cudaFuncAttributeMaxDynamicSharedMemorySize, SM_ISTA);
    k_ista<<<NCTA, 512, SM_ISTA>>>(y);             // 3

    k_out<<<(8 * 3 * 256 * 256 + 255) / 256, 256>>>(out);  // 4
}